// round 14
// baseline (speedup 1.0000x reference)
#include <cuda_runtime.h>
#include <cuda_bf16.h>
#include <math.h>
#include <stdint.h>

// Problem constants (fixed shapes)
constexpr int NN = 100000;   // nodes
constexpr int EE = 1000000;  // edges
constexpr int DD = 80;       // hidden dim
constexpr int HH = 8;        // heads
constexpr int DK = 10;       // per-head dim
constexpr int LL = 10;       // layers

// per-layer converted-weight layout (elements): q0 k6400 v12800 o19200 w1 25600 w2 38400
constexpr int WPL = 51200;

// ---------------- device scratch (no allocations allowed) ----------------
__device__ __nv_bfloat16 g_hhi[(size_t)NN * 80];
__device__ __nv_bfloat16 g_hlo[(size_t)NN * 80];
__device__ __nv_bfloat16 g_athi[(size_t)NN * 80];
__device__ __nv_bfloat16 g_atlo[(size_t)NN * 80];
__device__ __nv_bfloat16 g_whi[(size_t)LL * WPL];
__device__ __nv_bfloat16 g_wlo[(size_t)LL * WPL];
__device__ float g_qkv[(size_t)NN * 240];   // q:0..79 k:80..159 v:160..239
__device__ float g_r0[NN * 40];
__device__ float g_r1[NN * 20];
__device__ int g_cnt[NN];
__device__ int g_off[NN + 1];
__device__ int g_cur[NN];
__device__ int g_ssrc[EE];

// ================= PTX helpers (sm_80+ baseline features only) ========
__device__ __forceinline__ uint32_t smem_u32(const void* p) {
    uint32_t a;
    asm("{ .reg .u64 t; cvta.to.shared.u64 t, %1; cvt.u32.u64 %0, t; }" : "=r"(a) : "l"(p));
    return a;
}
__device__ __forceinline__ void ldsm_x4(uint32_t* r, uint32_t a) {
    asm volatile("ldmatrix.sync.aligned.m8n8.x4.shared.b16 {%0,%1,%2,%3}, [%4];"
                 : "=r"(r[0]), "=r"(r[1]), "=r"(r[2]), "=r"(r[3]) : "r"(a));
}
__device__ __forceinline__ void ldsm_x4t(uint32_t* r, uint32_t a) {
    asm volatile("ldmatrix.sync.aligned.m8n8.x4.trans.shared.b16 {%0,%1,%2,%3}, [%4];"
                 : "=r"(r[0]), "=r"(r[1]), "=r"(r[2]), "=r"(r[3]) : "r"(a));
}
__device__ __forceinline__ void mma16816(float* d, const uint32_t* a, const uint32_t* b) {
    asm volatile("mma.sync.aligned.m16n8k16.row.col.f32.bf16.bf16.f32 "
                 "{%0,%1,%2,%3}, {%4,%5,%6,%7}, {%8,%9}, {%0,%1,%2,%3};"
                 : "+f"(d[0]), "+f"(d[1]), "+f"(d[2]), "+f"(d[3])
                 : "r"(a[0]), "r"(a[1]), "r"(a[2]), "r"(a[3]), "r"(b[0]), "r"(b[1]));
}
__device__ __forceinline__ void cpa16(uint32_t smem, const void* g) {
    asm volatile("cp.async.cg.shared.global [%0], [%1], 16;" :: "r"(smem), "l"(g));
}
__device__ __forceinline__ void cpa_commit() {
    asm volatile("cp.async.commit_group;");
}
__device__ __forceinline__ void cpa_wait_all() {
    asm volatile("cp.async.wait_group 0;" ::: "memory");
}
__device__ __forceinline__ uint32_t split_pack(float x, float y, uint32_t& lo) {
    __nv_bfloat16 hx = __float2bfloat16(x), hy = __float2bfloat16(y);
    __nv_bfloat16 lx = __float2bfloat16(x - __bfloat162float(hx));
    __nv_bfloat16 ly = __float2bfloat16(y - __bfloat162float(hy));
    __nv_bfloat162 lp; lp.x = lx; lp.y = ly;
    lo = *(uint32_t*)&lp;
    __nv_bfloat162 hp; hp.x = hx; hp.y = hy;
    return *(uint32_t*)&hp;
}
__device__ __forceinline__ float2 join2(const __nv_bfloat16* hi, const __nv_bfloat16* lo) {
    __nv_bfloat162 h = *(const __nv_bfloat162*)hi;
    __nv_bfloat162 l = *(const __nv_bfloat162*)lo;
    float2 r;
    r.x = __bfloat162float(h.x) + __bfloat162float(l.x);
    r.y = __bfloat162float(h.y) + __bfloat162float(l.y);
    return r;
}
__device__ __forceinline__ float2 unjoin(uint32_t hi, uint32_t lo) {
    __nv_bfloat162 h = *(__nv_bfloat162*)&hi;
    __nv_bfloat162 l = *(__nv_bfloat162*)&lo;
    float2 r;
    r.x = __bfloat162float(h.x) + __bfloat162float(l.x);
    r.y = __bfloat162float(h.y) + __bfloat162float(l.y);
    return r;
}

constexpr int LDS = 88;  // padded bf16 row stride (conflict-free ldmatrix)

// ---------------- weight pre-conversion (all weights, one launch) -------------
__global__ void conv_all(const float* __restrict__ Wq, const float* __restrict__ Wk,
                         const float* __restrict__ Wv, const float* __restrict__ Wo,
                         const float* __restrict__ W1, const float* __restrict__ W2) {
    int t = blockIdx.x * blockDim.x + threadIdx.x;
    if (t >= LL * WPL) return;
    int l = t / WPL, i = t - l * WPL;
    float w;
    if (i < 6400)        w = Wq[l * 6400 + i];
    else if (i < 12800)  w = Wk[l * 6400 + i - 6400];
    else if (i < 19200)  w = Wv[l * 6400 + i - 12800];
    else if (i < 25600)  w = Wo[l * 6400 + i - 19200];
    else if (i < 38400)  w = W1[l * 12800 + i - 25600];
    else                 w = W2[l * 12800 + i - 38400];
    __nv_bfloat16 h = __float2bfloat16(w);
    g_whi[t] = h;
    g_wlo[t] = __float2bfloat16(w - __bfloat162float(h));
}

// ================= QKV GEMM (layer 0 only; K=80, NB=3, fp32 out [N,240]) ======
__global__ void __launch_bounds__(256, 2)
qkv_gemm(const __nv_bfloat16* __restrict__ Ahi, const __nv_bfloat16* __restrict__ Alo,
         const __nv_bfloat16* __restrict__ Whi, const __nv_bfloat16* __restrict__ Wlo,
         float* __restrict__ Cf, int M) {
    extern __shared__ char dsm[];
    constexpr uint32_t SAB = 128 * LDS * 2;   // 22528
    constexpr uint32_t SBB = 80 * LDS * 2;    // 14080
    constexpr uint32_t SLOT = 2 * SBB;        // 28160
    constexpr uint32_t BBASE = 2 * SAB;       // 45056

    const uint32_t sb = smem_u32(dsm);
    const int tid = threadIdx.x, warp = tid >> 5, lane = tid & 31;
    const int row0 = blockIdx.x * 128;

    {
        const int r = tid >> 1, half = tid & 1;
        const int gr = row0 + r;
        const uint32_t sm0 = sb + (uint32_t)(r * LDS + half * 40) * 2;
        if (gr < M) {
            const char* gh = (const char*)(Ahi + (size_t)gr * 80 + half * 40);
            const char* gl = (const char*)(Alo + (size_t)gr * 80 + half * 40);
#pragma unroll
            for (int q = 0; q < 5; q++) {
                cpa16(sm0 + q * 16, gh + q * 16);
                cpa16(sm0 + SAB + q * 16, gl + q * 16);
            }
        } else {
            uint4 z = {0, 0, 0, 0};
#pragma unroll
            for (int q = 0; q < 5; q++) {
                *(uint4*)(dsm + (r * LDS + half * 40) * 2 + q * 16) = z;
                *(uint4*)(dsm + SAB + (r * LDS + half * 40) * 2 + q * 16) = z;
            }
        }
    }
    auto stageB = [&](int nb, int s) {
        const uint32_t base = sb + BBASE + s * SLOT;
        for (int idx = tid; idx < 800; idx += 256) {
            int k = idx / 10, q = idx - k * 10;
            uint32_t soff = (uint32_t)(k * LDS + q * 8) * 2;
            cpa16(base + soff, Whi + nb * 6400 + k * 80 + q * 8);
            cpa16(base + SBB + soff, Wlo + nb * 6400 + k * 80 + q * 8);
        }
    };
    stageB(0, 0);
    stageB(1, 1);
    cpa_commit();
    cpa_wait_all();
    __syncthreads();

    const int wrow = warp * 16;
    const int jj = lane >> 3, ri = lane & 7;
    const int ra = wrow + ri + ((jj & 1) << 3);
    const int caoff = (jj >> 1) << 3;
    const int rb = lane & 15;
    const int nq = (lane >> 4) << 3;
    const int g = lane >> 2, tig = lane & 3;
    const int r0g = row0 + wrow + g;
    const int r1g = r0g + 8;

    uint32_t ahf[5][4], alf[5][4];
#pragma unroll
    for (int kc = 0; kc < 5; kc++) {
        uint32_t aoff = ((uint32_t)ra * LDS + kc * 16 + caoff) * 2;
        ldsm_x4(ahf[kc], sb + aoff);
        ldsm_x4(alf[kc], sb + SAB + aoff);
    }

    auto compute = [&](int nb, int s) {
        float acc[10][4];
#pragma unroll
        for (int nt = 0; nt < 10; nt++)
#pragma unroll
            for (int i = 0; i < 4; i++) acc[nt][i] = 0.f;
        const uint32_t bbase = sb + BBASE + s * SLOT;
#pragma unroll
        for (int kc = 0; kc < 5; kc++) {
            const uint32_t kg = kc * 16 + rb;
#pragma unroll
            for (int ntp = 0; ntp < 5; ntp++) {
                uint32_t boff = (kg * LDS + ntp * 16 + nq) * 2;
                uint32_t bh[4], bl[4];
                ldsm_x4t(bh, bbase + boff);
                ldsm_x4t(bl, bbase + SBB + boff);
                mma16816(acc[2 * ntp], ahf[kc], &bh[0]);
                mma16816(acc[2 * ntp], ahf[kc], &bl[0]);
                mma16816(acc[2 * ntp], alf[kc], &bh[0]);
                mma16816(acc[2 * ntp + 1], ahf[kc], &bh[2]);
                mma16816(acc[2 * ntp + 1], ahf[kc], &bl[2]);
                mma16816(acc[2 * ntp + 1], alf[kc], &bh[2]);
            }
        }
#pragma unroll
        for (int nt = 0; nt < 10; nt++) {
            int c = nb * 80 + nt * 8 + tig * 2;
            if (r0g < M) {
                float2 o; o.x = acc[nt][0]; o.y = acc[nt][1];
                *(float2*)(Cf + (size_t)r0g * 240 + c) = o;
            }
            if (r1g < M) {
                float2 o; o.x = acc[nt][2]; o.y = acc[nt][3];
                *(float2*)(Cf + (size_t)r1g * 240 + c) = o;
            }
        }
    };

    compute(0, 0);
    compute(1, 1);
    __syncthreads();
    stageB(2, 0);
    cpa_commit();
    cpa_wait_all();
    __syncthreads();
    compute(2, 0);
}

// ======= mega-fused: h''=h+attn@Wo+bo; h''+=relu(h''@W1+b1)@W2+b2;
//         then QKV(next layer) = h''@[Wq|Wk|Wv]  (h'' never re-read from gmem)
__global__ void __launch_bounds__(256)
ofn_fused(const __nv_bfloat16* __restrict__ Ahi, const __nv_bfloat16* __restrict__ Alo,
          const __nv_bfloat16* __restrict__ Whi, const __nv_bfloat16* __restrict__ Wlo,
          const float* __restrict__ bo, const float* __restrict__ b1,
          const float* __restrict__ b2,
          const __nv_bfloat16* __restrict__ NWhi, const __nv_bfloat16* __restrict__ NWlo,
          float* __restrict__ Qkv, int doqkv,
          __nv_bfloat16* __restrict__ Hhi, __nv_bfloat16* __restrict__ Hlo, int M) {
    extern __shared__ char dsm[];
    constexpr uint32_t SAB = 22528;           // one A array
    constexpr uint32_t SBB = 14080;           // one 80-row B array
    constexpr uint32_t S0 = 45056;
    constexpr uint32_t SLOT = 28160;
    // slots: s0 Wo->Wq, s1 W1a->Wk, s2 W1b->Wv, s3 W2hi, s4 W2lo; total 185856

    const uint32_t sb = smem_u32(dsm);
    const int tid = threadIdx.x, warp = tid >> 5, lane = tid & 31;
    const int row0 = blockIdx.x * 128;

    auto slot = [&](int s) { return sb + S0 + (uint32_t)s * SLOT; };
    auto stage80 = [&](int s, const __nv_bfloat16* hi, const __nv_bfloat16* lo) {
        const uint32_t base = slot(s);
        for (int idx = tid; idx < 800; idx += 256) {
            int k = idx / 10, q = idx - k * 10;
            uint32_t soff = (uint32_t)(k * LDS + q * 8) * 2;
            cpa16(base + soff, hi + k * 80 + q * 8);
            cpa16(base + SBB + soff, lo + k * 80 + q * 8);
        }
    };
    auto stage160 = [&](int s, const __nv_bfloat16* p) {
        const uint32_t base = slot(s);
        for (int idx = tid; idx < 1600; idx += 256) {
            int k = idx / 10, q = idx - k * 10;
            uint32_t soff = (uint32_t)(k * LDS + q * 8) * 2;
            cpa16(base + soff, p + k * 80 + q * 8);
        }
    };

    // ---- A stage (attn split) ----
    {
        const int r = tid >> 1, half = tid & 1;
        const int gr = row0 + r;
        const uint32_t sm0 = sb + (uint32_t)(r * LDS + half * 40) * 2;
        if (gr < M) {
            const char* gh = (const char*)(Ahi + (size_t)gr * 80 + half * 40);
            const char* gl = (const char*)(Alo + (size_t)gr * 80 + half * 40);
#pragma unroll
            for (int q = 0; q < 5; q++) {
                cpa16(sm0 + q * 16, gh + q * 16);
                cpa16(sm0 + SAB + q * 16, gl + q * 16);
            }
        } else {
            uint4 z = {0, 0, 0, 0};
#pragma unroll
            for (int q = 0; q < 5; q++) {
                *(uint4*)(dsm + (r * LDS + half * 40) * 2 + q * 16) = z;
                *(uint4*)(dsm + SAB + (r * LDS + half * 40) * 2 + q * 16) = z;
            }
        }
    }
    stage80(0, Whi + 19200, Wlo + 19200);   // Wo
    // W1 [80,160] into s1/s2
    for (int idx = tid; idx < 1600; idx += 256) {
        int k = idx / 20, q = idx - k * 20;
        int nb = q / 10, nq8 = q - nb * 10;
        uint32_t soff = (uint32_t)(k * LDS + nq8 * 8) * 2;
        cpa16(slot(1 + nb) + soff, Whi + 25600 + k * 160 + q * 8);
        cpa16(slot(1 + nb) + SBB + soff, Wlo + 25600 + k * 160 + q * 8);
    }
    stage160(3, Whi + 38400);               // W2 hi
    stage160(4, Wlo + 38400);               // W2 lo
    cpa_commit();
    cpa_wait_all();
    __syncthreads();

    const int wrow = warp * 16;
    const int jj = lane >> 3, ri = lane & 7;
    const int ra = wrow + ri + ((jj & 1) << 3);
    const int caoff = (jj >> 1) << 3;
    const int rb = lane & 15;
    const int nq = (lane >> 4) << 3;
    const int g = lane >> 2, tig = lane & 3;
    const int r0g = row0 + wrow + g;
    const int r1g = r0g + 8;

    // ---- O-proj mainloop (s0) ----
    float accO[10][4];
#pragma unroll
    for (int nt = 0; nt < 10; nt++)
#pragma unroll
        for (int i = 0; i < 4; i++) accO[nt][i] = 0.f;
#pragma unroll
    for (int kc = 0; kc < 5; kc++) {
        uint32_t aoff = ((uint32_t)ra * LDS + kc * 16 + caoff) * 2;
        uint32_t ah[4], al[4];
        ldsm_x4(ah, sb + aoff);
        ldsm_x4(al, sb + SAB + aoff);
        const uint32_t kg = kc * 16 + rb;
#pragma unroll
        for (int ntp = 0; ntp < 5; ntp++) {
            uint32_t boff = (kg * LDS + ntp * 16 + nq) * 2;
            uint32_t bh[4], bl[4];
            ldsm_x4t(bh, slot(0) + boff);
            ldsm_x4t(bl, slot(0) + SBB + boff);
            mma16816(accO[2 * ntp], ah, &bh[0]);
            mma16816(accO[2 * ntp], ah, &bl[0]);
            mma16816(accO[2 * ntp], al, &bh[0]);
            mma16816(accO[2 * ntp + 1], ah, &bh[2]);
            mma16816(accO[2 * ntp + 1], ah, &bl[2]);
            mma16816(accO[2 * ntp + 1], al, &bh[2]);
        }
    }

    // ---- O epilogue: h' = accO + bo + h -> fragments ih/il ----
    uint32_t ih[5][4], il[5][4];
#pragma unroll
    for (int nt = 0; nt < 10; nt++) {
        int c = nt * 8 + tig * 2;
        float b0 = bo[c], b1v = bo[c + 1];
        float v0 = accO[nt][0] + b0, v1 = accO[nt][1] + b1v;
        float v2 = accO[nt][2] + b0, v3 = accO[nt][3] + b1v;
        if (r0g < M) {
            float2 rv = join2(Hhi + (size_t)r0g * 80 + c, Hlo + (size_t)r0g * 80 + c);
            v0 += rv.x; v1 += rv.y;
        }
        if (r1g < M) {
            float2 rv = join2(Hhi + (size_t)r1g * 80 + c, Hlo + (size_t)r1g * 80 + c);
            v2 += rv.x; v3 += rv.y;
        }
        int i = nt >> 1, hf = (nt & 1) << 1;
        uint32_t lo0, lo1;
        ih[i][hf + 0] = split_pack(v0, v1, lo0);
        ih[i][hf + 1] = split_pack(v2, v3, lo1);
        il[i][hf + 0] = lo0;
        il[i][hf + 1] = lo1;
    }

    // s0 free -> prefetch next-layer Wq (overlaps FFN1)
    __syncthreads();
    if (doqkv) { stage80(0, NWhi + 0, NWlo + 0); cpa_commit(); }

    // ---- FFN1: I = h' @ W1 (s1, s2) ----
    float acc1[20][4];
#pragma unroll
    for (int nt = 0; nt < 20; nt++)
#pragma unroll
        for (int i = 0; i < 4; i++) acc1[nt][i] = 0.f;

#pragma unroll 1
    for (int nb = 0; nb < 2; nb++) {
        const uint32_t bslot = slot(1 + nb);
#pragma unroll
        for (int kc = 0; kc < 5; kc++) {
            const uint32_t kg = kc * 16 + rb;
#pragma unroll
            for (int ntp = 0; ntp < 5; ntp++) {
                uint32_t boff = (kg * LDS + ntp * 16 + nq) * 2;
                uint32_t bh[4], bl[4];
                ldsm_x4t(bh, bslot + boff);
                ldsm_x4t(bl, bslot + SBB + boff);
                float* a0 = acc1[nb * 10 + 2 * ntp];
                float* a1 = acc1[nb * 10 + 2 * ntp + 1];
                mma16816(a0, ih[kc], &bh[0]);
                mma16816(a0, ih[kc], &bl[0]);
                mma16816(a0, il[kc], &bh[0]);
                mma16816(a1, ih[kc], &bh[2]);
                mma16816(a1, ih[kc], &bl[2]);
                mma16816(a1, il[kc], &bh[2]);
            }
        }
    }

    // s1/s2 free -> prefetch next-layer Wk, Wv (overlaps FFN2)
    __syncthreads();
    if (doqkv) {
        stage80(1, NWhi + 6400, NWlo + 6400);
        stage80(2, NWhi + 12800, NWlo + 12800);
        cpa_commit();
    }

    // ---- bias + ReLU + re-split ----
    uint32_t i2h[10][4], i2l[10][4];
#pragma unroll
    for (int t = 0; t < 20; t++) {
        int c = t * 8 + tig * 2;
        float b0 = b1[c], bb1 = b1[c + 1];
        float v0 = fmaxf(acc1[t][0] + b0, 0.f);
        float v1 = fmaxf(acc1[t][1] + bb1, 0.f);
        float v2 = fmaxf(acc1[t][2] + b0, 0.f);
        float v3 = fmaxf(acc1[t][3] + bb1, 0.f);
        int i = t >> 1, hf = (t & 1) << 1;
        uint32_t lo0, lo1;
        i2h[i][hf + 0] = split_pack(v0, v1, lo0);
        i2h[i][hf + 1] = split_pack(v2, v3, lo1);
        i2l[i][hf + 0] = lo0;
        i2l[i][hf + 1] = lo1;
    }

    // ---- FFN2 (K=160, s3/s4) ----
    float acc2[10][4];
#pragma unroll
    for (int nt = 0; nt < 10; nt++)
#pragma unroll
        for (int i = 0; i < 4; i++) acc2[nt][i] = 0.f;

#pragma unroll
    for (int kc = 0; kc < 10; kc++) {
        const uint32_t kg = kc * 16 + rb;
#pragma unroll
        for (int ntp = 0; ntp < 5; ntp++) {
            uint32_t boff = (kg * LDS + ntp * 16 + nq) * 2;
            uint32_t bh[4], bl[4];
            ldsm_x4t(bh, slot(3) + boff);
            ldsm_x4t(bl, slot(4) + boff);
            mma16816(acc2[2 * ntp], i2h[kc], &bh[0]);
            mma16816(acc2[2 * ntp], i2h[kc], &bl[0]);
            mma16816(acc2[2 * ntp], i2l[kc], &bh[0]);
            mma16816(acc2[2 * ntp + 1], i2h[kc], &bh[2]);
            mma16816(acc2[2 * ntp + 1], i2h[kc], &bl[2]);
            mma16816(acc2[2 * ntp + 1], i2l[kc], &bh[2]);
        }
    }

    // ---- final epilogue: h'' = acc2 + b2 + h'; store split; build h'' frags --
    uint32_t i3h[5][4], i3l[5][4];
#pragma unroll
    for (int nt = 0; nt < 10; nt++) {
        int c = nt * 8 + tig * 2;
        float b0 = b2[c], bb = b2[c + 1];
        int i = nt >> 1, hf = (nt & 1) << 1;
        float2 hp0 = unjoin(ih[i][hf + 0], il[i][hf + 0]);
        float2 hp1 = unjoin(ih[i][hf + 1], il[i][hf + 1]);
        float v0 = acc2[nt][0] + b0 + hp0.x;
        float v1 = acc2[nt][1] + bb + hp0.y;
        float v2 = acc2[nt][2] + b0 + hp1.x;
        float v3 = acc2[nt][3] + bb + hp1.y;
        uint32_t lo0, lo1;
        uint32_t hi0 = split_pack(v0, v1, lo0);
        uint32_t hi1 = split_pack(v2, v3, lo1);
        i3h[i][hf + 0] = hi0; i3l[i][hf + 0] = lo0;
        i3h[i][hf + 1] = hi1; i3l[i][hf + 1] = lo1;
        if (r0g < M) {
            *(uint32_t*)(Hhi + (size_t)r0g * 80 + c) = hi0;
            *(uint32_t*)(Hlo + (size_t)r0g * 80 + c) = lo0;
        }
        if (r1g < M) {
            *(uint32_t*)(Hhi + (size_t)r1g * 80 + c) = hi1;
            *(uint32_t*)(Hlo + (size_t)r1g * 80 + c) = lo1;
        }
    }

    // ---- QKV (next layer): out = h'' @ [Wq|Wk|Wv], fp32 [N,240] ----
    if (!doqkv) return;
    cpa_wait_all();
    __syncthreads();

#pragma unroll 1
    for (int nb = 0; nb < 3; nb++) {
        float acc[10][4];
#pragma unroll
        for (int nt = 0; nt < 10; nt++)
#pragma unroll
            for (int i = 0; i < 4; i++) acc[nt][i] = 0.f;
        const uint32_t bslot = slot(nb);
#pragma unroll
        for (int kc = 0; kc < 5; kc++) {
            const uint32_t kg = kc * 16 + rb;
#pragma unroll
            for (int ntp = 0; ntp < 5; ntp++) {
                uint32_t boff = (kg * LDS + ntp * 16 + nq) * 2;
                uint32_t bh[4], bl[4];
                ldsm_x4t(bh, bslot + boff);
                ldsm_x4t(bl, bslot + SBB + boff);
                mma16816(acc[2 * ntp], i3h[kc], &bh[0]);
                mma16816(acc[2 * ntp], i3h[kc], &bl[0]);
                mma16816(acc[2 * ntp], i3l[kc], &bh[0]);
                mma16816(acc[2 * ntp + 1], i3h[kc], &bh[2]);
                mma16816(acc[2 * ntp + 1], i3h[kc], &bl[2]);
                mma16816(acc[2 * ntp + 1], i3l[kc], &bh[2]);
            }
        }
#pragma unroll
        for (int nt = 0; nt < 10; nt++) {
            int c = nb * 80 + nt * 8 + tig * 2;
            if (r0g < M) {
                float2 o; o.x = acc[nt][0]; o.y = acc[nt][1];
                *(float2*)(Qkv + (size_t)r0g * 240 + c) = o;
            }
            if (r1g < M) {
                float2 o; o.x = acc[nt][2]; o.y = acc[nt][3];
                *(float2*)(Qkv + (size_t)r1g * 240 + c) = o;
            }
        }
    }
}

// ---------------- CSR build ----------------
__global__ void zero_cnt_kernel() {
    int t = blockIdx.x * blockDim.x + threadIdx.x;
    if (t < NN) g_cnt[t] = 0;
}
__global__ void hist_kernel(const int* __restrict__ dst) {
    int e = blockIdx.x * blockDim.x + threadIdx.x;
    if (e < EE) atomicAdd(&g_cnt[dst[e]], 1);
}
__global__ void scan_kernel() {
    __shared__ int sums[1024];
    const int t = threadIdx.x;
    const int CH = (NN + 1023) / 1024;
    int b = t * CH;
    int e2 = b + CH; if (e2 > NN) e2 = NN;
    int s = 0;
    for (int i = b; i < e2; i++) s += g_cnt[i];
    sums[t] = s;
    __syncthreads();
    for (int ofs = 1; ofs < 1024; ofs <<= 1) {
        int v = (t >= ofs) ? sums[t - ofs] : 0;
        __syncthreads();
        sums[t] += v;
        __syncthreads();
    }
    int run = (t > 0) ? sums[t - 1] : 0;
    for (int i = b; i < e2; i++) {
        g_off[i] = run; g_cur[i] = run; run += g_cnt[i];
    }
    if (t == 1023) g_off[NN] = run;
}
__global__ void scatter_kernel(const int* __restrict__ src, const int* __restrict__ dst) {
    int e = blockIdx.x * blockDim.x + threadIdx.x;
    if (e >= EE) return;
    int d = dst[e];
    int p = atomicAdd(&g_cur[d], 1);
    g_ssrc[p] = src[e];
}

// ---------------- fused attention: thread = (node, head) ----------------
__global__ void __launch_bounds__(256) attn_fused() {
    __shared__ float sq[32 * 80];
    __shared__ float so[32 * 80];
    const int tid = threadIdx.x;
    const int node0 = blockIdx.x * 32;

    for (int idx = tid; idx < 2560; idx += 256) {
        int nl = idx / 80, d = idx - nl * 80;
        sq[idx] = g_qkv[(size_t)(node0 + nl) * 240 + d];
    }
    __syncthreads();

    const int nl = tid >> 3;
    const int h = tid & 7;
    const int node = node0 + nl;
    float q[10];
#pragma unroll
    for (int k = 0; k < 10; k++) q[k] = sq[nl * 80 + h * 10 + k];

    const int beg = g_off[node];
    const int end = g_off[node + 1];
    float z = 0.f, wv[10];
#pragma unroll
    for (int k = 0; k < 10; k++) wv[k] = 0.f;

    for (int jj = beg; jj < end; jj++) {
        int s = g_ssrc[jj];
        const float2* kp = (const float2*)(g_qkv + (size_t)s * 240 + 80 + h * 10);
        float2 k0 = kp[0], k1 = kp[1], k2 = kp[2], k3 = kp[3], k4 = kp[4];
        float dot = fmaf(k0.x, q[0], fmaf(k0.y, q[1], fmaf(k1.x, q[2], fmaf(k1.y, q[3],
                    fmaf(k2.x, q[4], fmaf(k2.y, q[5], fmaf(k3.x, q[6], fmaf(k3.y, q[7],
                    fmaf(k4.x, q[8], k4.y * q[9])))))))));
        dot = fminf(fmaxf(dot * 0.31622776601683794f, -5.f), 5.f);
        float sc = __expf(dot);
        z += sc;
        const float2* vp = kp + 40;
        float2 v0 = vp[0], v1 = vp[1], v2 = vp[2], v3 = vp[3], v4 = vp[4];
        wv[0] = fmaf(sc, v0.x, wv[0]); wv[1] = fmaf(sc, v0.y, wv[1]);
        wv[2] = fmaf(sc, v1.x, wv[2]); wv[3] = fmaf(sc, v1.y, wv[3]);
        wv[4] = fmaf(sc, v2.x, wv[4]); wv[5] = fmaf(sc, v2.y, wv[5]);
        wv[6] = fmaf(sc, v3.x, wv[6]); wv[7] = fmaf(sc, v3.y, wv[7]);
        wv[8] = fmaf(sc, v4.x, wv[8]); wv[9] = fmaf(sc, v4.y, wv[9]);
    }
    float inv = 1.f / (z + 1e-6f);
#pragma unroll
    for (int k = 0; k < 10; k++) so[nl * 80 + h * 10 + k] = wv[k] * inv;
    __syncthreads();

    for (int idx = tid; idx < 2560; idx += 256) {
        float v = so[idx];
        __nv_bfloat16 hv = __float2bfloat16(v);
        g_athi[(size_t)node0 * 80 + idx] = hv;
        g_atlo[(size_t)node0 * 80 + idx] = __float2bfloat16(v - __bfloat162float(hv));
    }
}

// ---------------- fp32 tiled GEMM (embedding, K=9, split out) ----------------
__global__ void __launch_bounds__(256)
embed_gemm(const float* __restrict__ A, const float* __restrict__ W,
           const float* __restrict__ bias, int M) {
    constexpr int KT = 9, NC = 80;
    __shared__ __align__(16) float Ws[KT * NC];
    __shared__ __align__(16) float As[KT * 64];
    const int tid = threadIdx.x;
    const int tx = tid & 15;
    const int ty = tid >> 4;
    const int row0 = blockIdx.x * 64;
    float acc[4][5];
#pragma unroll
    for (int i = 0; i < 4; i++)
#pragma unroll
        for (int j = 0; j < 5; j++) acc[i][j] = 0.f;
    for (int idx = tid; idx < KT * NC; idx += 256) Ws[idx] = W[idx];
    for (int idx = tid; idx < 64 * KT; idx += 256) {
        int r = idx / KT, kk = idx - r * KT;
        int gr = row0 + r;
        As[kk * 64 + r] = (gr < M) ? A[gr * KT + kk] : 0.f;
    }
    __syncthreads();
#pragma unroll
    for (int k = 0; k < KT; ++k) {
        float4 av = *reinterpret_cast<const float4*>(&As[k * 64 + ty * 4]);
#pragma unroll
        for (int j = 0; j < 5; ++j) {
            float w = Ws[k * NC + tx + j * 16];
            acc[0][j] = fmaf(av.x, w, acc[0][j]);
            acc[1][j] = fmaf(av.y, w, acc[1][j]);
            acc[2][j] = fmaf(av.z, w, acc[2][j]);
            acc[3][j] = fmaf(av.w, w, acc[3][j]);
        }
    }
#pragma unroll
    for (int i = 0; i < 4; i++) {
        int gr = row0 + ty * 4 + i;
        if (gr >= M) break;
#pragma unroll
        for (int j = 0; j < 5; j++) {
            int c = tx + j * 16;
            float v = acc[i][j] + bias[c];
            __nv_bfloat16 hv = __float2bfloat16(v);
            g_hhi[(size_t)gr * 80 + c] = hv;
            g_hlo[(size_t)gr * 80 + c] = __float2bfloat16(v - __bfloat162float(hv));
        }
    }
}

// ---------------- small FC (readout) ----------------
template <int K, int NC, bool RELU>
__global__ void simple_fc(const float* __restrict__ A, const float* __restrict__ W,
                          const float* __restrict__ b, float* __restrict__ C, int M) {
    int t = blockIdx.x * blockDim.x + threadIdx.x;
    if (t >= M * NC) return;
    int row = t / NC;
    int col = t - row * NC;
    float acc = b[col];
    const float* ap = A + (size_t)row * K;
#pragma unroll 4
    for (int k = 0; k < K; k++) acc = fmaf(ap[k], W[k * NC + col], acc);
    if (RELU) acc = fmaxf(acc, 0.f);
    C[t] = acc;
}
__global__ void fc_split_in(const float* __restrict__ W, const float* __restrict__ b,
                            float* __restrict__ C, int M) {
    int t = blockIdx.x * blockDim.x + threadIdx.x;
    if (t >= M * 40) return;
    int row = t / 40;
    int col = t - row * 40;
    float acc = b[col];
    const __nv_bfloat16* hh = g_hhi + (size_t)row * 80;
    const __nv_bfloat16* hl = g_hlo + (size_t)row * 80;
#pragma unroll 4
    for (int k = 0; k < 80; k++) {
        float a = __bfloat162float(hh[k]) + __bfloat162float(hl[k]);
        acc = fmaf(a, W[k * 40 + col], acc);
    }
    C[t] = fmaxf(acc, 0.f);
}

// ---------------- launcher ----------------
extern "C" void kernel_launch(void* const* d_in, const int* in_sizes, int n_in,
                              void* d_out, int out_size) {
    const float* x   = (const float*)d_in[0];
    const int*   ei  = (const int*)d_in[1];
    const float* We  = (const float*)d_in[2];
    const float* be  = (const float*)d_in[3];
    const float* Wq  = (const float*)d_in[4];
    const float* Wk  = (const float*)d_in[5];
    const float* Wv  = (const float*)d_in[6];
    const float* Wo  = (const float*)d_in[7];
    const float* bo  = (const float*)d_in[8];
    const float* W1  = (const float*)d_in[9];
    const float* b1  = (const float*)d_in[10];
    const float* W2  = (const float*)d_in[11];
    const float* b2  = (const float*)d_in[12];
    const float* Wr0 = (const float*)d_in[13];
    const float* br0 = (const float*)d_in[14];
    const float* Wr1 = (const float*)d_in[15];
    const float* br1 = (const float*)d_in[16];
    const float* Wr2 = (const float*)d_in[17];
    const float* br2 = (const float*)d_in[18];
    float* out = (float*)d_out;

    const int* src = ei;
    const int* dst = ei + EE;

    __nv_bfloat16 *p_hhi, *p_hlo, *p_athi, *p_atlo, *p_whi, *p_wlo;
    float *p_qkv, *p_r0, *p_r1;
    cudaGetSymbolAddress((void**)&p_hhi, g_hhi);
    cudaGetSymbolAddress((void**)&p_hlo, g_hlo);
    cudaGetSymbolAddress((void**)&p_athi, g_athi);
    cudaGetSymbolAddress((void**)&p_atlo, g_atlo);
    cudaGetSymbolAddress((void**)&p_whi, g_whi);
    cudaGetSymbolAddress((void**)&p_wlo, g_wlo);
    cudaGetSymbolAddress((void**)&p_qkv, g_qkv);
    cudaGetSymbolAddress((void**)&p_r0, g_r0);
    cudaGetSymbolAddress((void**)&p_r1, g_r1);

    constexpr int S_QKV = 45056 + 2 * 28160;   // 101376
    constexpr int S_OFN = 45056 + 5 * 28160;   // 185856
    cudaFuncSetAttribute((const void*)qkv_gemm,
                         cudaFuncAttributeMaxDynamicSharedMemorySize, S_QKV);
    cudaFuncSetAttribute((const void*)ofn_fused,
                         cudaFuncAttributeMaxDynamicSharedMemorySize, S_OFN);

    const int TILES = (NN + 127) / 128;  // 782

    conv_all<<<(LL * WPL + 255) / 256, 256>>>(Wq, Wk, Wv, Wo, W1, W2);   // 1
    embed_gemm<<<(NN + 63) / 64, 256>>>(x, We, be, NN);                   // 2
    zero_cnt_kernel<<<(NN + 255) / 256, 256>>>();                         // 3
    qkv_gemm<<<TILES, 256, S_QKV>>>(p_hhi, p_hlo, p_whi, p_wlo, p_qkv, NN); // 4 (profiled)
    hist_kernel<<<(EE + 255) / 256, 256>>>(dst);                          // 5
    scan_kernel<<<1, 1024>>>();                                           // 6
    scatter_kernel<<<(EE + 255) / 256, 256>>>(src, dst);                  // 7

    for (int l = 0; l < LL; l++) {
        const __nv_bfloat16* whi = p_whi + (size_t)l * WPL;
        const __nv_bfloat16* wlo = p_wlo + (size_t)l * WPL;
        const int doqkv = (l + 1 < LL) ? 1 : 0;
        const __nv_bfloat16* nwhi = p_whi + (size_t)(l + doqkv) * WPL;
        const __nv_bfloat16* nwlo = p_wlo + (size_t)(l + doqkv) * WPL;

        attn_fused<<<NN / 32, 256>>>();

        ofn_fused<<<TILES, 256, S_OFN>>>(
            p_athi, p_atlo, whi, wlo,
            bo + (size_t)l * DD, b1 + (size_t)l * 2 * DD, b2 + (size_t)l * DD,
            nwhi, nwlo, p_qkv, doqkv,
            p_hhi, p_hlo, NN);
    }

    // --- readout 80 -> 40 -> 20 -> 4 ---
    fc_split_in<<<(NN * 40 + 255) / 256, 256>>>(Wr0, br0, p_r0, NN);
    simple_fc<40, 20, true><<<(NN * 20 + 255) / 256, 256>>>(p_r0, Wr1, br1, p_r1, NN);
    simple_fc<20, 4, false><<<(NN * 4 + 255) / 256, 256>>>(p_r1, Wr2, br2, out, NN);
}

// round 15
// speedup vs baseline: 1.0389x; 1.0389x over previous
#include <cuda_runtime.h>
#include <cuda_bf16.h>
#include <math.h>
#include <stdint.h>

// Problem constants (fixed shapes)
constexpr int NN = 100000;   // nodes
constexpr int EE = 1000000;  // edges
constexpr int DD = 80;       // hidden dim
constexpr int LL = 10;       // layers

// per-layer converted-weight layout (elements): q0 k6400 v12800 o19200 w1 25600 w2 38400
constexpr int WPL = 51200;

// ---------------- device scratch (no allocations allowed) ----------------
__device__ __nv_bfloat16 g_hhi[(size_t)NN * 80];
__device__ __nv_bfloat16 g_hlo[(size_t)NN * 80];
__device__ __nv_bfloat16 g_athi[(size_t)NN * 80];
__device__ __nv_bfloat16 g_atlo[(size_t)NN * 80];
__device__ __nv_bfloat16 g_whi[(size_t)LL * WPL];
__device__ __nv_bfloat16 g_wlo[(size_t)LL * WPL];
__device__ float g_q[(size_t)NN * 80];
__device__ float g_kv[(size_t)NN * 160];   // k:0..79 v:80..159
__device__ float g_r0[NN * 40];
__device__ float g_r1[NN * 20];
__device__ int g_cnt[NN];
__device__ int g_off[NN + 1];
__device__ int g_cur[NN];
__device__ int g_ssrc[EE];

// ================= PTX helpers (sm_80+ baseline features only) ========
__device__ __forceinline__ uint32_t smem_u32(const void* p) {
    uint32_t a;
    asm("{ .reg .u64 t; cvta.to.shared.u64 t, %1; cvt.u32.u64 %0, t; }" : "=r"(a) : "l"(p));
    return a;
}
__device__ __forceinline__ void ldsm_x4(uint32_t* r, uint32_t a) {
    asm volatile("ldmatrix.sync.aligned.m8n8.x4.shared.b16 {%0,%1,%2,%3}, [%4];"
                 : "=r"(r[0]), "=r"(r[1]), "=r"(r[2]), "=r"(r[3]) : "r"(a));
}
__device__ __forceinline__ void ldsm_x4t(uint32_t* r, uint32_t a) {
    asm volatile("ldmatrix.sync.aligned.m8n8.x4.trans.shared.b16 {%0,%1,%2,%3}, [%4];"
                 : "=r"(r[0]), "=r"(r[1]), "=r"(r[2]), "=r"(r[3]) : "r"(a));
}
__device__ __forceinline__ void mma16816(float* d, const uint32_t* a, const uint32_t* b) {
    asm volatile("mma.sync.aligned.m16n8k16.row.col.f32.bf16.bf16.f32 "
                 "{%0,%1,%2,%3}, {%4,%5,%6,%7}, {%8,%9}, {%0,%1,%2,%3};"
                 : "+f"(d[0]), "+f"(d[1]), "+f"(d[2]), "+f"(d[3])
                 : "r"(a[0]), "r"(a[1]), "r"(a[2]), "r"(a[3]), "r"(b[0]), "r"(b[1]));
}
__device__ __forceinline__ void cpa16(uint32_t smem, const void* g) {
    asm volatile("cp.async.cg.shared.global [%0], [%1], 16;" :: "r"(smem), "l"(g));
}
__device__ __forceinline__ void cpa_commit() {
    asm volatile("cp.async.commit_group;");
}
__device__ __forceinline__ void cpa_wait_all() {
    asm volatile("cp.async.wait_group 0;" ::: "memory");
}
__device__ __forceinline__ void cpa_wait_1() {
    asm volatile("cp.async.wait_group 1;" ::: "memory");
}
__device__ __forceinline__ uint32_t split_pack(float x, float y, uint32_t& lo) {
    __nv_bfloat16 hx = __float2bfloat16(x), hy = __float2bfloat16(y);
    __nv_bfloat16 lx = __float2bfloat16(x - __bfloat162float(hx));
    __nv_bfloat16 ly = __float2bfloat16(y - __bfloat162float(hy));
    __nv_bfloat162 lp; lp.x = lx; lp.y = ly;
    lo = *(uint32_t*)&lp;
    __nv_bfloat162 hp; hp.x = hx; hp.y = hy;
    return *(uint32_t*)&hp;
}
__device__ __forceinline__ float2 join2(const __nv_bfloat16* hi, const __nv_bfloat16* lo) {
    __nv_bfloat162 h = *(const __nv_bfloat162*)hi;
    __nv_bfloat162 l = *(const __nv_bfloat162*)lo;
    float2 r;
    r.x = __bfloat162float(h.x) + __bfloat162float(l.x);
    r.y = __bfloat162float(h.y) + __bfloat162float(l.y);
    return r;
}
__device__ __forceinline__ float2 unjoin(uint32_t hi, uint32_t lo) {
    __nv_bfloat162 h = *(__nv_bfloat162*)&hi;
    __nv_bfloat162 l = *(__nv_bfloat162*)&lo;
    float2 r;
    r.x = __bfloat162float(h.x) + __bfloat162float(l.x);
    r.y = __bfloat162float(h.y) + __bfloat162float(l.y);
    return r;
}

constexpr int LDS = 88;  // padded bf16 row stride (conflict-free ldmatrix)

// ---------------- weight pre-conversion (all weights, one launch) -------------
__global__ void conv_all(const float* __restrict__ Wq, const float* __restrict__ Wk,
                         const float* __restrict__ Wv, const float* __restrict__ Wo,
                         const float* __restrict__ W1, const float* __restrict__ W2) {
    int t = blockIdx.x * blockDim.x + threadIdx.x;
    if (t >= LL * WPL) return;
    int l = t / WPL, i = t - l * WPL;
    float w;
    if (i < 6400)        w = Wq[l * 6400 + i];
    else if (i < 12800)  w = Wk[l * 6400 + i - 6400];
    else if (i < 19200)  w = Wv[l * 6400 + i - 12800];
    else if (i < 25600)  w = Wo[l * 6400 + i - 19200];
    else if (i < 38400)  w = W1[l * 12800 + i - 25600];
    else                 w = W2[l * 12800 + i - 38400];
    __nv_bfloat16 h = __float2bfloat16(w);
    g_whi[t] = h;
    g_wlo[t] = __float2bfloat16(w - __bfloat162float(h));
}

// ================= QKV GEMM (K=80, NB=3, fp32 out Q[N,80] + KV[N,160]) ========
__global__ void __launch_bounds__(256, 2)
qkv_gemm(const __nv_bfloat16* __restrict__ Ahi, const __nv_bfloat16* __restrict__ Alo,
         const __nv_bfloat16* __restrict__ Whi, const __nv_bfloat16* __restrict__ Wlo,
         float* __restrict__ Qf, float* __restrict__ KVf, int M) {
    extern __shared__ char dsm[];
    constexpr uint32_t SAB = 128 * LDS * 2;   // 22528
    constexpr uint32_t SBB = 80 * LDS * 2;    // 14080
    constexpr uint32_t SLOT = 2 * SBB;        // 28160
    constexpr uint32_t BBASE = 2 * SAB;       // 45056

    const uint32_t sb = smem_u32(dsm);
    const int tid = threadIdx.x, warp = tid >> 5, lane = tid & 31;
    const int row0 = blockIdx.x * 128;

    {
        const int r = tid >> 1, half = tid & 1;
        const int gr = row0 + r;
        const uint32_t sm0 = sb + (uint32_t)(r * LDS + half * 40) * 2;
        if (gr < M) {
            const char* gh = (const char*)(Ahi + (size_t)gr * 80 + half * 40);
            const char* gl = (const char*)(Alo + (size_t)gr * 80 + half * 40);
#pragma unroll
            for (int q = 0; q < 5; q++) {
                cpa16(sm0 + q * 16, gh + q * 16);
                cpa16(sm0 + SAB + q * 16, gl + q * 16);
            }
        } else {
            uint4 z = {0, 0, 0, 0};
#pragma unroll
            for (int q = 0; q < 5; q++) {
                *(uint4*)(dsm + (r * LDS + half * 40) * 2 + q * 16) = z;
                *(uint4*)(dsm + SAB + (r * LDS + half * 40) * 2 + q * 16) = z;
            }
        }
    }
    auto stageB = [&](int nb, int s) {
        const uint32_t base = sb + BBASE + s * SLOT;
        for (int idx = tid; idx < 800; idx += 256) {
            int k = idx / 10, q = idx - k * 10;
            uint32_t soff = (uint32_t)(k * LDS + q * 8) * 2;
            cpa16(base + soff, Whi + nb * 6400 + k * 80 + q * 8);
            cpa16(base + SBB + soff, Wlo + nb * 6400 + k * 80 + q * 8);
        }
    };
    stageB(0, 0);
    stageB(1, 1);
    cpa_commit();
    cpa_wait_all();
    __syncthreads();

    const int wrow = warp * 16;
    const int jj = lane >> 3, ri = lane & 7;
    const int ra = wrow + ri + ((jj & 1) << 3);
    const int caoff = (jj >> 1) << 3;
    const int rb = lane & 15;
    const int nq = (lane >> 4) << 3;
    const int g = lane >> 2, tig = lane & 3;
    const int r0g = row0 + wrow + g;
    const int r1g = r0g + 8;

    uint32_t ahf[5][4], alf[5][4];
#pragma unroll
    for (int kc = 0; kc < 5; kc++) {
        uint32_t aoff = ((uint32_t)ra * LDS + kc * 16 + caoff) * 2;
        ldsm_x4(ahf[kc], sb + aoff);
        ldsm_x4(alf[kc], sb + SAB + aoff);
    }

    auto compute = [&](int nb, int s) {
        float acc[10][4];
#pragma unroll
        for (int nt = 0; nt < 10; nt++)
#pragma unroll
            for (int i = 0; i < 4; i++) acc[nt][i] = 0.f;
        const uint32_t bbase = sb + BBASE + s * SLOT;
#pragma unroll
        for (int kc = 0; kc < 5; kc++) {
            const uint32_t kg = kc * 16 + rb;
#pragma unroll
            for (int ntp = 0; ntp < 5; ntp++) {
                uint32_t boff = (kg * LDS + ntp * 16 + nq) * 2;
                uint32_t bh[4], bl[4];
                ldsm_x4t(bh, bbase + boff);
                ldsm_x4t(bl, bbase + SBB + boff);
                mma16816(acc[2 * ntp], ahf[kc], &bh[0]);
                mma16816(acc[2 * ntp], ahf[kc], &bl[0]);
                mma16816(acc[2 * ntp], alf[kc], &bh[0]);
                mma16816(acc[2 * ntp + 1], ahf[kc], &bh[2]);
                mma16816(acc[2 * ntp + 1], ahf[kc], &bl[2]);
                mma16816(acc[2 * ntp + 1], alf[kc], &bh[2]);
            }
        }
#pragma unroll
        for (int nt = 0; nt < 10; nt++) {
            int cl = nt * 8 + tig * 2;
#pragma unroll
            for (int hrow = 0; hrow < 2; hrow++) {
                int gr = hrow ? r1g : r0g;
                if (gr >= M) continue;
                float2 o;
                o.x = acc[nt][hrow * 2 + 0];
                o.y = acc[nt][hrow * 2 + 1];
                if (nb == 0) *(float2*)(Qf + (size_t)gr * 80 + cl) = o;
                else         *(float2*)(KVf + (size_t)gr * 160 + (nb - 1) * 80 + cl) = o;
            }
        }
    };

    compute(0, 0);
    compute(1, 1);
    __syncthreads();
    stageB(2, 0);
    cpa_commit();
    cpa_wait_all();
    __syncthreads();
    compute(2, 0);
}

// ======= fused O-proj + FFN, 2 CTA/SM: h''=h+attn@Wo+bo; h''+=relu(h''@W1+b1)@W2+b2
__global__ void __launch_bounds__(256, 2)
ofn_fused(const __nv_bfloat16* __restrict__ Ahi, const __nv_bfloat16* __restrict__ Alo,
          const __nv_bfloat16* __restrict__ Whi, const __nv_bfloat16* __restrict__ Wlo,
          const float* __restrict__ bo, const float* __restrict__ b1,
          const float* __restrict__ b2,
          __nv_bfloat16* __restrict__ Hhi, __nv_bfloat16* __restrict__ Hlo, int M) {
    extern __shared__ char dsm[];
    constexpr uint32_t SAB = 22528;   // one A array
    constexpr uint32_t SBB = 14080;   // one 80-row B array
    constexpr uint32_t AREG = 0;      // [0,45056): A hi/lo; later W1b hi/lo
    constexpr uint32_t S0 = 45056;    // Wo hi/lo; later W2hi (160 rows)
    constexpr uint32_t S1 = 73216;    // W1a hi/lo; later W2lo (160 rows)
    // total 101376 -> 2 CTAs/SM

    const uint32_t sb = smem_u32(dsm);
    const int tid = threadIdx.x, warp = tid >> 5, lane = tid & 31;
    const int row0 = blockIdx.x * 128;

    // ---- A stage (attn split) ----
    {
        const int r = tid >> 1, half = tid & 1;
        const int gr = row0 + r;
        const uint32_t sm0 = sb + (uint32_t)(r * LDS + half * 40) * 2;
        if (gr < M) {
            const char* gh = (const char*)(Ahi + (size_t)gr * 80 + half * 40);
            const char* gl = (const char*)(Alo + (size_t)gr * 80 + half * 40);
#pragma unroll
            for (int q = 0; q < 5; q++) {
                cpa16(sm0 + q * 16, gh + q * 16);
                cpa16(sm0 + SAB + q * 16, gl + q * 16);
            }
        } else {
            uint4 z = {0, 0, 0, 0};
#pragma unroll
            for (int q = 0; q < 5; q++) {
                *(uint4*)(dsm + (r * LDS + half * 40) * 2 + q * 16) = z;
                *(uint4*)(dsm + SAB + (r * LDS + half * 40) * 2 + q * 16) = z;
            }
        }
    }
    // ---- Wo -> S0 ----
    for (int idx = tid; idx < 800; idx += 256) {
        int k = idx / 10, q = idx - k * 10;
        uint32_t soff = (uint32_t)(k * LDS + q * 8) * 2;
        cpa16(sb + S0 + soff, Whi + 19200 + k * 80 + q * 8);
        cpa16(sb + S0 + SBB + soff, Wlo + 19200 + k * 80 + q * 8);
    }
    // ---- W1a (cols 0..79) -> S1 ----
    for (int idx = tid; idx < 800; idx += 256) {
        int k = idx / 10, q = idx - k * 10;
        uint32_t soff = (uint32_t)(k * LDS + q * 8) * 2;
        cpa16(sb + S1 + soff, Whi + 25600 + k * 160 + q * 8);
        cpa16(sb + S1 + SBB + soff, Wlo + 25600 + k * 160 + q * 8);
    }
    cpa_commit();
    cpa_wait_all();
    __syncthreads();

    const int wrow = warp * 16;
    const int jj = lane >> 3, ri = lane & 7;
    const int ra = wrow + ri + ((jj & 1) << 3);
    const int caoff = (jj >> 1) << 3;
    const int rb = lane & 15;
    const int nq = (lane >> 4) << 3;
    const int g = lane >> 2, tig = lane & 3;
    const int r0g = row0 + wrow + g;
    const int r1g = r0g + 8;

    // ---- preload ALL A fragments -> A region becomes free ----
    uint32_t ahf[5][4], alf[5][4];
#pragma unroll
    for (int kc = 0; kc < 5; kc++) {
        uint32_t aoff = ((uint32_t)ra * LDS + kc * 16 + caoff) * 2;
        ldsm_x4(ahf[kc], sb + aoff);
        ldsm_x4(alf[kc], sb + SAB + aoff);
    }
    __syncthreads();

    // ---- restage W1b (cols 80..159) into A region (G1), overlaps O-proj ----
    for (int idx = tid; idx < 800; idx += 256) {
        int k = idx / 10, q = idx - k * 10;
        uint32_t soff = (uint32_t)(k * LDS + q * 8) * 2;
        cpa16(sb + AREG + soff, Whi + 25600 + k * 160 + 80 + q * 8);
        cpa16(sb + AREG + SBB + soff, Wlo + 25600 + k * 160 + 80 + q * 8);
    }
    cpa_commit();   // G1

    // ---- O-proj mainloop (S0) ----
    float accO[10][4];
#pragma unroll
    for (int nt = 0; nt < 10; nt++)
#pragma unroll
        for (int i = 0; i < 4; i++) accO[nt][i] = 0.f;
#pragma unroll
    for (int kc = 0; kc < 5; kc++) {
        const uint32_t kg = kc * 16 + rb;
#pragma unroll
        for (int ntp = 0; ntp < 5; ntp++) {
            uint32_t boff = (kg * LDS + ntp * 16 + nq) * 2;
            uint32_t bh[4], bl[4];
            ldsm_x4t(bh, sb + S0 + boff);
            ldsm_x4t(bl, sb + S0 + SBB + boff);
            mma16816(accO[2 * ntp], ahf[kc], &bh[0]);
            mma16816(accO[2 * ntp], ahf[kc], &bl[0]);
            mma16816(accO[2 * ntp], alf[kc], &bh[0]);
            mma16816(accO[2 * ntp + 1], ahf[kc], &bh[2]);
            mma16816(accO[2 * ntp + 1], ahf[kc], &bl[2]);
            mma16816(accO[2 * ntp + 1], alf[kc], &bh[2]);
        }
    }

    // ---- O epilogue: h' = accO + bo + h -> fragments ih/il ----
    uint32_t ih[5][4], il[5][4];
#pragma unroll
    for (int nt = 0; nt < 10; nt++) {
        int c = nt * 8 + tig * 2;
        float b0 = bo[c], b1v = bo[c + 1];
        float v0 = accO[nt][0] + b0, v1 = accO[nt][1] + b1v;
        float v2 = accO[nt][2] + b0, v3 = accO[nt][3] + b1v;
        if (r0g < M) {
            float2 rv = join2(Hhi + (size_t)r0g * 80 + c, Hlo + (size_t)r0g * 80 + c);
            v0 += rv.x; v1 += rv.y;
        }
        if (r1g < M) {
            float2 rv = join2(Hhi + (size_t)r1g * 80 + c, Hlo + (size_t)r1g * 80 + c);
            v2 += rv.x; v3 += rv.y;
        }
        int i = nt >> 1, hf = (nt & 1) << 1;
        uint32_t lo0, lo1;
        ih[i][hf + 0] = split_pack(v0, v1, lo0);
        ih[i][hf + 1] = split_pack(v2, v3, lo1);
        il[i][hf + 0] = lo0;
        il[i][hf + 1] = lo1;
    }

    // ---- all warps done reading S0 -> restage W2hi into S0 (G2) ----
    __syncthreads();
    for (int idx = tid; idx < 1600; idx += 256) {
        int k = idx / 10, q = idx - k * 10;
        cpa16(sb + S0 + (uint32_t)(k * LDS + q * 8) * 2, Whi + 38400 + k * 80 + q * 8);
    }
    cpa_commit();   // G2

    // ---- FFN1-blk0 (S1 = W1a) -> acc1[0..9] ----
    float acc1[20][4];
#pragma unroll
    for (int nt = 0; nt < 20; nt++)
#pragma unroll
        for (int i = 0; i < 4; i++) acc1[nt][i] = 0.f;

#pragma unroll
    for (int kc = 0; kc < 5; kc++) {
        const uint32_t kg = kc * 16 + rb;
#pragma unroll
        for (int ntp = 0; ntp < 5; ntp++) {
            uint32_t boff = (kg * LDS + ntp * 16 + nq) * 2;
            uint32_t bh[4], bl[4];
            ldsm_x4t(bh, sb + S1 + boff);
            ldsm_x4t(bl, sb + S1 + SBB + boff);
            mma16816(acc1[2 * ntp], ih[kc], &bh[0]);
            mma16816(acc1[2 * ntp], ih[kc], &bl[0]);
            mma16816(acc1[2 * ntp], il[kc], &bh[0]);
            mma16816(acc1[2 * ntp + 1], ih[kc], &bh[2]);
            mma16816(acc1[2 * ntp + 1], ih[kc], &bl[2]);
            mma16816(acc1[2 * ntp + 1], il[kc], &bh[2]);
        }
    }

    // ---- wait W1b (G1); all warps past blk0 ----
    cpa_wait_1();
    __syncthreads();

    // ---- FFN1-blk1 (AREG = W1b) -> acc1[10..19] ----
#pragma unroll
    for (int kc = 0; kc < 5; kc++) {
        const uint32_t kg = kc * 16 + rb;
#pragma unroll
        for (int ntp = 0; ntp < 5; ntp++) {
            uint32_t boff = (kg * LDS + ntp * 16 + nq) * 2;
            uint32_t bh[4], bl[4];
            ldsm_x4t(bh, sb + AREG + boff);
            ldsm_x4t(bl, sb + AREG + SBB + boff);
            mma16816(acc1[10 + 2 * ntp], ih[kc], &bh[0]);
            mma16816(acc1[10 + 2 * ntp], ih[kc], &bl[0]);
            mma16816(acc1[10 + 2 * ntp], il[kc], &bh[0]);
            mma16816(acc1[10 + 2 * ntp + 1], ih[kc], &bh[2]);
            mma16816(acc1[10 + 2 * ntp + 1], ih[kc], &bl[2]);
            mma16816(acc1[10 + 2 * ntp + 1], il[kc], &bh[2]);
        }
    }

    // ---- restage W2lo into S1 (safe: all warps past blk0 via mid-sync) (G3) --
    for (int idx = tid; idx < 1600; idx += 256) {
        int k = idx / 10, q = idx - k * 10;
        cpa16(sb + S1 + (uint32_t)(k * LDS + q * 8) * 2, Wlo + 38400 + k * 80 + q * 8);
    }
    cpa_commit();   // G3

    // ---- bias + ReLU + re-split (overlaps W2 staging) ----
    uint32_t i2h[10][4], i2l[10][4];
#pragma unroll
    for (int t = 0; t < 20; t++) {
        int c = t * 8 + tig * 2;
        float b0 = b1[c], bb1 = b1[c + 1];
        float v0 = fmaxf(acc1[t][0] + b0, 0.f);
        float v1 = fmaxf(acc1[t][1] + bb1, 0.f);
        float v2 = fmaxf(acc1[t][2] + b0, 0.f);
        float v3 = fmaxf(acc1[t][3] + bb1, 0.f);
        int i = t >> 1, hf = (t & 1) << 1;
        uint32_t lo0, lo1;
        i2h[i][hf + 0] = split_pack(v0, v1, lo0);
        i2h[i][hf + 1] = split_pack(v2, v3, lo1);
        i2l[i][hf + 0] = lo0;
        i2l[i][hf + 1] = lo1;
    }
    cpa_wait_all();
    __syncthreads();

    // ---- FFN2 (K=160): hi in S0, lo in S1 ----
    float acc2[10][4];
#pragma unroll
    for (int nt = 0; nt < 10; nt++)
#pragma unroll
        for (int i = 0; i < 4; i++) acc2[nt][i] = 0.f;

#pragma unroll
    for (int kc = 0; kc < 10; kc++) {
        const uint32_t kg = kc * 16 + rb;
#pragma unroll
        for (int ntp = 0; ntp < 5; ntp++) {
            uint32_t boff = (kg * LDS + ntp * 16 + nq) * 2;
            uint32_t bh[4], bl[4];
            ldsm_x4t(bh, sb + S0 + boff);
            ldsm_x4t(bl, sb + S1 + boff);
            mma16816(acc2[2 * ntp], i2h[kc], &bh[0]);
            mma16816(acc2[2 * ntp], i2h[kc], &bl[0]);
            mma16816(acc2[2 * ntp], i2l[kc], &bh[0]);
            mma16816(acc2[2 * ntp + 1], i2h[kc], &bh[2]);
            mma16816(acc2[2 * ntp + 1], i2h[kc], &bl[2]);
            mma16816(acc2[2 * ntp + 1], i2l[kc], &bh[2]);
        }
    }

    // ---- final epilogue: h'' = acc2 + b2 + h' (unpacked from ih/il) ----
#pragma unroll
    for (int nt = 0; nt < 10; nt++) {
        int c = nt * 8 + tig * 2;
        float b0 = b2[c], bb = b2[c + 1];
        int i = nt >> 1, hf = (nt & 1) << 1;
        float2 hp0 = unjoin(ih[i][hf + 0], il[i][hf + 0]);
        float2 hp1 = unjoin(ih[i][hf + 1], il[i][hf + 1]);
        if (r0g < M) {
            float v0 = acc2[nt][0] + b0 + hp0.x;
            float v1 = acc2[nt][1] + bb + hp0.y;
            uint32_t lo;
            uint32_t hi = split_pack(v0, v1, lo);
            *(uint32_t*)(Hhi + (size_t)r0g * 80 + c) = hi;
            *(uint32_t*)(Hlo + (size_t)r0g * 80 + c) = lo;
        }
        if (r1g < M) {
            float v0 = acc2[nt][2] + b0 + hp1.x;
            float v1 = acc2[nt][3] + bb + hp1.y;
            uint32_t lo;
            uint32_t hi = split_pack(v0, v1, lo);
            *(uint32_t*)(Hhi + (size_t)r1g * 80 + c) = hi;
            *(uint32_t*)(Hlo + (size_t)r1g * 80 + c) = lo;
        }
    }
}

// ---------------- CSR build ----------------
__global__ void zero_cnt_kernel() {
    int t = blockIdx.x * blockDim.x + threadIdx.x;
    if (t < NN) g_cnt[t] = 0;
}
__global__ void hist_kernel(const int* __restrict__ dst) {
    int e = blockIdx.x * blockDim.x + threadIdx.x;
    if (e < EE) atomicAdd(&g_cnt[dst[e]], 1);
}
__global__ void scan_kernel() {
    __shared__ int sums[1024];
    const int t = threadIdx.x;
    const int CH = (NN + 1023) / 1024;
    int b = t * CH;
    int e2 = b + CH; if (e2 > NN) e2 = NN;
    int s = 0;
    for (int i = b; i < e2; i++) s += g_cnt[i];
    sums[t] = s;
    __syncthreads();
    for (int ofs = 1; ofs < 1024; ofs <<= 1) {
        int v = (t >= ofs) ? sums[t - ofs] : 0;
        __syncthreads();
        sums[t] += v;
        __syncthreads();
    }
    int run = (t > 0) ? sums[t - 1] : 0;
    for (int i = b; i < e2; i++) {
        g_off[i] = run; g_cur[i] = run; run += g_cnt[i];
    }
    if (t == 1023) g_off[NN] = run;
}
__global__ void scatter_kernel(const int* __restrict__ src, const int* __restrict__ dst) {
    int e = blockIdx.x * blockDim.x + threadIdx.x;
    if (e >= EE) return;
    int d = dst[e];
    int p = atomicAdd(&g_cur[d], 1);
    g_ssrc[p] = src[e];
}

// ---------------- fused attention: thread = (node, head) ----------------
__global__ void __launch_bounds__(256) attn_fused() {
    __shared__ float sq[32 * 80];
    __shared__ float so[32 * 80];
    const int tid = threadIdx.x;
    const int node0 = blockIdx.x * 32;

    for (int idx = tid; idx < 2560; idx += 256)
        sq[idx] = g_q[(size_t)node0 * 80 + idx];
    __syncthreads();

    const int nl = tid >> 3;
    const int h = tid & 7;
    const int node = node0 + nl;
    float q[10];
#pragma unroll
    for (int k = 0; k < 10; k++) q[k] = sq[nl * 80 + h * 10 + k];

    const int beg = g_off[node];
    const int end = g_off[node + 1];
    float z = 0.f, wv[10];
#pragma unroll
    for (int k = 0; k < 10; k++) wv[k] = 0.f;

    for (int jj = beg; jj < end; jj++) {
        int s = g_ssrc[jj];
        const float2* kp = (const float2*)(g_kv + (size_t)s * 160 + h * 10);
        float2 k0 = kp[0], k1 = kp[1], k2 = kp[2], k3 = kp[3], k4 = kp[4];
        float dot = fmaf(k0.x, q[0], fmaf(k0.y, q[1], fmaf(k1.x, q[2], fmaf(k1.y, q[3],
                    fmaf(k2.x, q[4], fmaf(k2.y, q[5], fmaf(k3.x, q[6], fmaf(k3.y, q[7],
                    fmaf(k4.x, q[8], k4.y * q[9])))))))));
        dot = fminf(fmaxf(dot * 0.31622776601683794f, -5.f), 5.f);
        float sc = __expf(dot);
        z += sc;
        const float2* vp = kp + 40;   // +80 floats
        float2 v0 = vp[0], v1 = vp[1], v2 = vp[2], v3 = vp[3], v4 = vp[4];
        wv[0] = fmaf(sc, v0.x, wv[0]); wv[1] = fmaf(sc, v0.y, wv[1]);
        wv[2] = fmaf(sc, v1.x, wv[2]); wv[3] = fmaf(sc, v1.y, wv[3]);
        wv[4] = fmaf(sc, v2.x, wv[4]); wv[5] = fmaf(sc, v2.y, wv[5]);
        wv[6] = fmaf(sc, v3.x, wv[6]); wv[7] = fmaf(sc, v3.y, wv[7]);
        wv[8] = fmaf(sc, v4.x, wv[8]); wv[9] = fmaf(sc, v4.y, wv[9]);
    }
    float inv = 1.f / (z + 1e-6f);
#pragma unroll
    for (int k = 0; k < 10; k++) so[nl * 80 + h * 10 + k] = wv[k] * inv;
    __syncthreads();

    for (int idx = tid; idx < 2560; idx += 256) {
        float v = so[idx];
        __nv_bfloat16 hv = __float2bfloat16(v);
        g_athi[(size_t)node0 * 80 + idx] = hv;
        g_atlo[(size_t)node0 * 80 + idx] = __float2bfloat16(v - __bfloat162float(hv));
    }
}

// ---------------- fp32 tiled GEMM (embedding, K=9, split out) ----------------
__global__ void __launch_bounds__(256)
embed_gemm(const float* __restrict__ A, const float* __restrict__ W,
           const float* __restrict__ bias, int M) {
    constexpr int KT = 9, NC = 80;
    __shared__ __align__(16) float Ws[KT * NC];
    __shared__ __align__(16) float As[KT * 64];
    const int tid = threadIdx.x;
    const int tx = tid & 15;
    const int ty = tid >> 4;
    const int row0 = blockIdx.x * 64;
    float acc[4][5];
#pragma unroll
    for (int i = 0; i < 4; i++)
#pragma unroll
        for (int j = 0; j < 5; j++) acc[i][j] = 0.f;
    for (int idx = tid; idx < KT * NC; idx += 256) Ws[idx] = W[idx];
    for (int idx = tid; idx < 64 * KT; idx += 256) {
        int r = idx / KT, kk = idx - r * KT;
        int gr = row0 + r;
        As[kk * 64 + r] = (gr < M) ? A[gr * KT + kk] : 0.f;
    }
    __syncthreads();
#pragma unroll
    for (int k = 0; k < KT; ++k) {
        float4 av = *reinterpret_cast<const float4*>(&As[k * 64 + ty * 4]);
#pragma unroll
        for (int j = 0; j < 5; ++j) {
            float w = Ws[k * NC + tx + j * 16];
            acc[0][j] = fmaf(av.x, w, acc[0][j]);
            acc[1][j] = fmaf(av.y, w, acc[1][j]);
            acc[2][j] = fmaf(av.z, w, acc[2][j]);
            acc[3][j] = fmaf(av.w, w, acc[3][j]);
        }
    }
#pragma unroll
    for (int i = 0; i < 4; i++) {
        int gr = row0 + ty * 4 + i;
        if (gr >= M) break;
#pragma unroll
        for (int j = 0; j < 5; j++) {
            int c = tx + j * 16;
            float v = acc[i][j] + bias[c];
            __nv_bfloat16 hv = __float2bfloat16(v);
            g_hhi[(size_t)gr * 80 + c] = hv;
            g_hlo[(size_t)gr * 80 + c] = __float2bfloat16(v - __bfloat162float(hv));
        }
    }
}

// ---------------- small FC (readout) ----------------
template <int K, int NC, bool RELU>
__global__ void simple_fc(const float* __restrict__ A, const float* __restrict__ W,
                          const float* __restrict__ b, float* __restrict__ C, int M) {
    int t = blockIdx.x * blockDim.x + threadIdx.x;
    if (t >= M * NC) return;
    int row = t / NC;
    int col = t - row * NC;
    float acc = b[col];
    const float* ap = A + (size_t)row * K;
#pragma unroll 4
    for (int k = 0; k < K; k++) acc = fmaf(ap[k], W[k * NC + col], acc);
    if (RELU) acc = fmaxf(acc, 0.f);
    C[t] = acc;
}
__global__ void fc_split_in(const float* __restrict__ W, const float* __restrict__ b,
                            float* __restrict__ C, int M) {
    int t = blockIdx.x * blockDim.x + threadIdx.x;
    if (t >= M * 40) return;
    int row = t / 40;
    int col = t - row * 40;
    float acc = b[col];
    const __nv_bfloat16* hh = g_hhi + (size_t)row * 80;
    const __nv_bfloat16* hl = g_hlo + (size_t)row * 80;
#pragma unroll 4
    for (int k = 0; k < 80; k++) {
        float a = __bfloat162float(hh[k]) + __bfloat162float(hl[k]);
        acc = fmaf(a, W[k * 40 + col], acc);
    }
    C[t] = fmaxf(acc, 0.f);
}

// ---------------- launcher ----------------
extern "C" void kernel_launch(void* const* d_in, const int* in_sizes, int n_in,
                              void* d_out, int out_size) {
    const float* x   = (const float*)d_in[0];
    const int*   ei  = (const int*)d_in[1];
    const float* We  = (const float*)d_in[2];
    const float* be  = (const float*)d_in[3];
    const float* Wq  = (const float*)d_in[4];
    const float* Wk  = (const float*)d_in[5];
    const float* Wv  = (const float*)d_in[6];
    const float* Wo  = (const float*)d_in[7];
    const float* bo  = (const float*)d_in[8];
    const float* W1  = (const float*)d_in[9];
    const float* b1  = (const float*)d_in[10];
    const float* W2  = (const float*)d_in[11];
    const float* b2  = (const float*)d_in[12];
    const float* Wr0 = (const float*)d_in[13];
    const float* br0 = (const float*)d_in[14];
    const float* Wr1 = (const float*)d_in[15];
    const float* br1 = (const float*)d_in[16];
    const float* Wr2 = (const float*)d_in[17];
    const float* br2 = (const float*)d_in[18];
    float* out = (float*)d_out;

    const int* src = ei;
    const int* dst = ei + EE;

    __nv_bfloat16 *p_hhi, *p_hlo, *p_athi, *p_atlo, *p_whi, *p_wlo;
    float *p_q, *p_kv, *p_r0, *p_r1;
    cudaGetSymbolAddress((void**)&p_hhi, g_hhi);
    cudaGetSymbolAddress((void**)&p_hlo, g_hlo);
    cudaGetSymbolAddress((void**)&p_athi, g_athi);
    cudaGetSymbolAddress((void**)&p_atlo, g_atlo);
    cudaGetSymbolAddress((void**)&p_whi, g_whi);
    cudaGetSymbolAddress((void**)&p_wlo, g_wlo);
    cudaGetSymbolAddress((void**)&p_q, g_q);
    cudaGetSymbolAddress((void**)&p_kv, g_kv);
    cudaGetSymbolAddress((void**)&p_r0, g_r0);
    cudaGetSymbolAddress((void**)&p_r1, g_r1);

    constexpr int S_QKV = 45056 + 2 * 28160;   // 101376
    constexpr int S_OFN = 101376;
    cudaFuncSetAttribute((const void*)qkv_gemm,
                         cudaFuncAttributeMaxDynamicSharedMemorySize, S_QKV);
    cudaFuncSetAttribute((const void*)ofn_fused,
                         cudaFuncAttributeMaxDynamicSharedMemorySize, S_OFN);

    const int TILES = (NN + 127) / 128;  // 782

    conv_all<<<(LL * WPL + 255) / 256, 256>>>(Wq, Wk, Wv, Wo, W1, W2);   // 1
    embed_gemm<<<(NN + 63) / 64, 256>>>(x, We, be, NN);                   // 2
    zero_cnt_kernel<<<(NN + 255) / 256, 256>>>();                         // 3
    qkv_gemm<<<TILES, 256, S_QKV>>>(p_hhi, p_hlo, p_whi, p_wlo, p_q, p_kv, NN); // 4 (profiled)
    hist_kernel<<<(EE + 255) / 256, 256>>>(dst);                          // 5
    scan_kernel<<<1, 1024>>>();                                           // 6
    scatter_kernel<<<(EE + 255) / 256, 256>>>(src, dst);                  // 7

    for (int l = 0; l < LL; l++) {
        const __nv_bfloat16* whi = p_whi + (size_t)l * WPL;
        const __nv_bfloat16* wlo = p_wlo + (size_t)l * WPL;

        if (l > 0)
            qkv_gemm<<<TILES, 256, S_QKV>>>(p_hhi, p_hlo, whi, wlo, p_q, p_kv, NN);

        attn_fused<<<NN / 32, 256>>>();

        ofn_fused<<<TILES, 256, S_OFN>>>(
            p_athi, p_atlo, whi, wlo,
            bo + (size_t)l * DD, b1 + (size_t)l * 2 * DD, b2 + (size_t)l * DD,
            p_hhi, p_hlo, NN);
    }

    // --- readout 80 -> 40 -> 20 -> 4 ---
    fc_split_in<<<(NN * 40 + 255) / 256, 256>>>(Wr0, br0, p_r0, NN);
    simple_fc<40, 20, true><<<(NN * 20 + 255) / 256, 256>>>(p_r0, Wr1, br1, p_r1, NN);
    simple_fc<20, 4, false><<<(NN * 4 + 255) / 256, 256>>>(p_r1, Wr2, br2, out, NN);
}